// round 6
// baseline (speedup 1.0000x reference)
#include <cuda_runtime.h>
#include <cstdint>

#define N_NODES 8192
#define N_COMM 16
#define DIMS 64

#define TILE_ROWS 32
#define TILE_COLS 512
#define N_TILES_R (N_NODES / TILE_ROWS)   // 256
#define N_TILES_C (N_NODES / TILE_COLS)   // 16
#define N_TILES (N_TILES_R * N_TILES_C)   // 4096
#define S2_GRID 592                        // 148 SMs * 4 blocks

// Scratch (no device allocation allowed) — fully rewritten every launch.
__device__ float g_pi[N_NODES * N_COMM];
__device__ __align__(16) float g_partI[N_TILES];
__device__ __align__(16) float g_partR[N_TILES];
__device__ int g_ticket;
__device__ int g_done;

// ---- packed f32x2 helpers (sm_103a; ptxas never emits these from C++) ----
__device__ __forceinline__ unsigned long long fma2(unsigned long long a,
                                                   unsigned long long b,
                                                   unsigned long long c) {
    unsigned long long d;
    asm("fma.rn.f32x2 %0, %1, %2, %3;" : "=l"(d) : "l"(a), "l"(b), "l"(c));
    return d;
}
__device__ __forceinline__ unsigned long long add2(unsigned long long a,
                                                   unsigned long long b) {
    unsigned long long d;
    asm("add.rn.f32x2 %0, %1, %2;" : "=l"(d) : "l"(a), "l"(b));
    return d;
}
__device__ __forceinline__ unsigned long long pack2(float x, float y) {
    unsigned long long r;
    asm("mov.b64 %0, {%1, %2};" : "=l"(r) : "f"(x), "f"(y));
    return r;
}
__device__ __forceinline__ float2 unpack2(unsigned long long v) {
    float2 f;
    asm("mov.b64 {%0, %1}, %2;" : "=f"(f.x), "=f"(f.y) : "l"(v));
    return f;
}

// ============================================================================
// Stage 1: distances over 3 manifolds -> dist_norm -> softmax -> g_pi
// Block handles 16 nodes. Coalesced float4 staging of node embeddings into
// padded smem (stride 196 floats: half-warp pair lands on different banks),
// then vectorized float4 compute per (node, k).
// Also resets the stage2 ticket/done counters (stream-ordered before stage2).
// ============================================================================
__global__ __launch_bounds__(256) void stage1(const float* __restrict__ ne,
                                              const float* __restrict__ comm) {
    __shared__ float sC[N_COMM * 68];            // [k][d], row padded to 68
    __shared__ float sX[16][3 * DIMS + 4];       // [node][l*64+d], stride 196
    int tid = threadIdx.x;

    if (blockIdx.x == 0 && tid == 0) { g_ticket = 0; g_done = 0; }

    // communities -> smem, [k][d] with padded rows (bank spread for LDS.128)
    for (int e = tid; e < N_COMM * DIMS; e += 256) {
        int k = e >> 6, d = e & 63;
        sC[k * 68 + d] = comm[e];
    }
    // node embeddings: 3 manifolds x 16 nodes x 64 dims, coalesced float4
    int n0 = blockIdx.x * 16;
#pragma unroll
    for (int l = 0; l < 3; ++l) {
        float4 v = *(const float4*)(ne + ((size_t)l * N_NODES + n0) * DIMS + tid * 4);
        int node = tid >> 4;
        int d = (tid & 15) * 4;
        *(float4*)&sX[node][l * DIMS + d] = v;
    }
    __syncthreads();

    int warp = tid >> 5, lane = tid & 31;
    int half = lane >> 4, k = lane & 15;
    int nl = warp * 2 + half;                    // node-local 0..15
    int node = n0 + nl;

    const float4* xE = (const float4*)&sX[nl][0];
    const float4* xL = (const float4*)&sX[nl][DIMS];
    const float4* xS = (const float4*)&sX[nl][2 * DIMS];
    const float4* cB = (const float4*)&sC[k * 68];

    float t0 = sX[nl][DIMS] * sC[k * 68];        // x1[0]*c[0] (Lorentz correction)
    float accE = 0.f, acc1 = 0.f, acc2 = 0.f;
#pragma unroll
    for (int d4 = 0; d4 < DIMS / 4; ++d4) {
        float4 c = cB[d4];
        float4 a0 = xE[d4], a1 = xL[d4], a2 = xS[d4];
        float dx = a0.x - c.x, dy = a0.y - c.y, dz = a0.z - c.z, dw = a0.w - c.w;
        accE = fmaf(dx, dx, accE); accE = fmaf(dy, dy, accE);
        accE = fmaf(dz, dz, accE); accE = fmaf(dw, dw, accE);
        acc1 = fmaf(a1.x, c.x, acc1); acc1 = fmaf(a1.y, c.y, acc1);
        acc1 = fmaf(a1.z, c.z, acc1); acc1 = fmaf(a1.w, c.w, acc1);
        acc2 = fmaf(a2.x, c.x, acc2); acc2 = fmaf(a2.y, c.y, acc2);
        acc2 = fmaf(a2.z, c.z, acc2); acc2 = fmaf(a2.w, c.w, acc2);
    }
    // Lorentz (kk=1): lip = <x,c> - 2*x0*c0 ; d = acosh(max(-lip, 1+eps))
    float lip = acc1 - 2.f * t0;
    float arg = fmaxf(-lip, 1.0000001f);         // f32 round of 1+1e-7
    float dl = acoshf(arg);
    // Sphere: d = acos(clip(<x,c>, -1+eps, 1-eps))
    float cs = fminf(fmaxf(acc2, -0.9999999f), 0.9999999f);
    float ds = acosf(cs);
    float dn = sqrtf(accE + dl * dl + ds * ds);  // L2 over manifolds

    // softmax over the 16 lanes of this half-warp
    float m = dn;
#pragma unroll
    for (int o = 8; o; o >>= 1) m = fmaxf(m, __shfl_xor_sync(0xffffffffu, m, o, 16));
    float e = expf(dn - m);
    float s = e;
#pragma unroll
    for (int o = 8; o; o >>= 1) s += __shfl_xor_sync(0xffffffffu, s, o, 16);

    g_pi[node * N_COMM + k] = e / s;
}

// ============================================================================
// Stage 2: streaming pass over ricci, work-stealing over 4096 tiles (32x512).
//   per tile: partI[t] = sum_ij R_ij * (pi_i . pi_j),  partR[t] = sum_ij R_ij
// Y-accumulation form: lane owns 2 j-cols; Y_j[m] += r_ij * pi_i[m]
// (16 independent f32x2 accumulators -> no RAW chains), fold with pi_j at
// tile end. pi_i broadcast via 4x LDS.128 per row. Deterministic: partials
// indexed by tile, per-tile order fixed, final reduce fixed order by the
// last-done block.
// ============================================================================
__global__ __launch_bounds__(256, 4) void stage2(const float* __restrict__ R,
                                                 const float* __restrict__ alpha,
                                                 float* __restrict__ out) {
    __shared__ __align__(16) float sPi[TILE_ROWS * N_COMM];   // 2 KB
    __shared__ float redI[8], redR[8];
    __shared__ int s_tile;
    __shared__ int s_last;

    int tid = threadIdx.x;
    int warp = tid >> 5, lane = tid & 31;
    const unsigned long long* gp = (const unsigned long long*)g_pi;

    for (;;) {
        if (tid == 0) s_tile = atomicAdd(&g_ticket, 1);
        __syncthreads();                                      // A
        int t = s_tile;
        if (t >= N_TILES) break;
        int it = t & (N_TILES_R - 1);                         // row-fastest: consecutive
        int jt = t >> 8;                                      // tickets share jt (L1 pi_j reuse)
        int i0 = it * TILE_ROWS;
        int jb = jt * TILE_COLS + warp * 64 + lane * 2;

        // stage pi rows [i0, i0+32) into shared (2 KB, float4)
        {
            const float4* src = (const float4*)(g_pi + (size_t)i0 * N_COMM);
            float4* dst = (float4*)sPi;
            if (tid < TILE_ROWS * N_COMM / 4) dst[tid] = src[tid];
        }
        __syncthreads();                                      // B

        const unsigned long long* Rp =
            (const unsigned long long*)(R + (size_t)i0 * N_NODES + jb);
        const ulonglong2* sq = (const ulonglong2*)sPi;

        unsigned long long Y0[8], Y1[8];
#pragma unroll
        for (int m = 0; m < 8; ++m) { Y0[m] = 0ull; Y1[m] = 0ull; }
        unsigned long long accR2 = 0ull;

#pragma unroll 4
        for (int i = 0; i < TILE_ROWS; ++i) {
            unsigned long long rv = __ldg(Rp + (size_t)i * (N_NODES / 2));
            float2 r = unpack2(rv);
            unsigned long long rx2 = pack2(r.x, r.x);
            unsigned long long ry2 = pack2(r.y, r.y);
            const ulonglong2* q = sq + i * 4;
#pragma unroll
            for (int m2 = 0; m2 < 4; ++m2) {
                ulonglong2 qv = q[m2];                        // LDS.128 broadcast
                Y0[2 * m2]     = fma2(qv.x, rx2, Y0[2 * m2]);
                Y1[2 * m2]     = fma2(qv.x, ry2, Y1[2 * m2]);
                Y0[2 * m2 + 1] = fma2(qv.y, rx2, Y0[2 * m2 + 1]);
                Y1[2 * m2 + 1] = fma2(qv.y, ry2, Y1[2 * m2 + 1]);
            }
            accR2 = add2(accR2, rv);
        }

        // fold: aI = sum_m Y0[m].pi_j0[m] + Y1[m].pi_j1[m]  (pi_j L1/L2-hot)
        unsigned long long accI2 = 0ull;
#pragma unroll
        for (int m = 0; m < 8; ++m) {
            accI2 = fma2(Y0[m], gp[(size_t)jb * 8 + m], accI2);
            accI2 = fma2(Y1[m], gp[(size_t)(jb + 1) * 8 + m], accI2);
        }
        float2 ai = unpack2(accI2); float aI = ai.x + ai.y;
        float2 ar = unpack2(accR2); float aR = ar.x + ar.y;
#pragma unroll
        for (int o = 16; o; o >>= 1) {
            aI += __shfl_xor_sync(0xffffffffu, aI, o);
            aR += __shfl_xor_sync(0xffffffffu, aR, o);
        }
        if (lane == 0) { redI[warp] = aI; redR[warp] = aR; }
        __syncthreads();                                      // C
        if (tid == 0) {
            float sI = 0.f, sR = 0.f;
#pragma unroll
            for (int w = 0; w < 8; ++w) { sI += redI[w]; sR += redR[w]; }
            g_partI[t] = sI;
            g_partR[t] = sR;
            __threadfence();
            int d = atomicAdd(&g_done, 1);
            s_last = (d == N_TILES - 1);
        }
        __syncthreads();                                      // D
        if (s_last) {
            // last block: deterministic fixed-order reduce of all tile partials
            __threadfence();
            const float4* pI = (const float4*)g_partI;
            const float4* pR = (const float4*)g_partR;
            float aI2 = 0.f, aR2 = 0.f;
            for (int b = tid; b < N_TILES / 4; b += 256) {
                float4 vi = pI[b], vr = pR[b];
                aI2 += (vi.x + vi.y) + (vi.z + vi.w);
                aR2 += (vr.x + vr.y) + (vr.z + vr.w);
            }
#pragma unroll
            for (int o = 16; o; o >>= 1) {
                aI2 += __shfl_xor_sync(0xffffffffu, aI2, o);
                aR2 += __shfl_xor_sync(0xffffffffu, aR2, o);
            }
            if (lane == 0) { redI[warp] = aI2; redR[warp] = aR2; }
            __syncthreads();                                  // E
            if (tid == 0) {
                float sI = 0.f, sR = 0.f;
#pragma unroll
                for (int w = 0; w < 8; ++w) { sI += redI[w]; sR += redR[w]; }
                // K*N = 131072 ; K*K*N = 2097152
                out[0] = alpha[0] * (sI / 131072.0f) - sR / 2097152.0f;
            }
        }
    }
}

extern "C" void kernel_launch(void* const* d_in, const int* in_sizes, int n_in,
                              void* d_out, int out_size) {
    const float* ne    = (const float*)d_in[0];  // (3, 8192, 64) f32
    const float* comm  = (const float*)d_in[1];  // (16, 64) f32
    const float* ricci = (const float*)d_in[2];  // (8192, 8192) f32
    const float* alpha = (const float*)d_in[3];  // scalar f32
    float* out = (float*)d_out;                  // 1 element f32

    stage1<<<N_NODES / 16, 256>>>(ne, comm);
    stage2<<<S2_GRID, 256>>>(ricci, alpha, out);
}